// round 7
// baseline (speedup 1.0000x reference)
#include <cuda_runtime.h>

#define BB 4096
#define PP 128
#define GG 128

#define SCX (8000.0f / 79.0f)
#define SCY (8000.0f / 79.0f)
#define SCZ (2000.0f / 19.0f)
#define BX (-4000.0f)
#define BY (-4000.0f)
#define BZ (0.0f)

#define DIST_THRESH_SQ (500.0f * 500.0f)
#define BBOX_THRESH 0.1f
#define EOFF 2.0e8f              // offset making e strictly positive
#define KEYMASK (~31)            // drop low 5 float bits, store q (q < 32)

typedef unsigned long long ull;

// ---- packed f32x2 helpers (sm_103a) ----
__device__ __forceinline__ ull pack2(float lo, float hi) {
    ull r;
    asm("mov.b64 %0, {%1, %2};" : "=l"(r) : "f"(lo), "f"(hi));
    return r;
}
__device__ __forceinline__ void unpack2(ull v, float& lo, float& hi) {
    asm("mov.b64 {%0, %1}, %2;" : "=f"(lo), "=f"(hi) : "l"(v));
}
__device__ __forceinline__ ull fma2(ull a, ull b, ull c) {
    ull r;
    asm("fma.rn.f32x2 %0, %1, %2, %3;" : "=l"(r) : "l"(a), "l"(b), "l"(c));
    return r;
}

// One warp per batch; each lane owns 4 proposals (lane, lane+32, lane+64, lane+96).
// No __syncthreads at all: warps are fully independent.
__global__ __launch_bounds__(128, 6)
void proposal_layer_kernel(const int*   __restrict__ topk_index,      // [B,P,3]
                           const float* __restrict__ topk_confs,      // [B,P]
                           const float* __restrict__ match_bbox_preds,// [B,P,2]
                           const float* __restrict__ roots_3d,        // [B,G,3]
                           const float* __restrict__ gt_bbox,         // [B,G,2]
                           const int*   __restrict__ num_person,      // [B]
                           float*       __restrict__ out)             // [B,P,7]
{
    const int w    = threadIdx.x >> 5;           // warp in CTA: 0..3
    const int lane = threadIdx.x & 31;
    const int b    = blockIdx.x * 4 + w;          // this warp's batch

    __shared__ __align__(16) float  s_nx[4][GG];  // -rx
    __shared__ __align__(16) float  s_ny[4][GG];  // -ry
    __shared__ __align__(16) float  s_nz[4][GG];  // -rz
    __shared__ __align__(16) float  s_h [4][GG];  // |r|^2/2 + EOFF
    __shared__ __align__(16) float2 s_bbox[4][GG];
    __shared__ __align__(16) float  s_out[4][PP * 7];

    float*  nx = s_nx[w];
    float*  ny = s_ny[w];
    float*  nz = s_nz[w];
    float*  hh = s_h [w];
    float2* bbx = s_bbox[w];

    // ---- stage this batch's gt data (4 g per lane) ----
    #pragma unroll
    for (int k = 0; k < 4; ++k) {
        const int g = lane + (k << 5);
        const float* r = roots_3d + ((size_t)b * GG + g) * 3;
        float rx = r[0], ry = r[1], rz = r[2];
        nx[g] = -rx;
        ny[g] = -ry;
        nz[g] = -rz;
        hh[g] = __fmaf_rn(0.5f, __fmaf_rn(rz, rz, __fmaf_rn(ry, ry, rx * rx)), EOFF);
        const float* gb = gt_bbox + ((size_t)b * GG + g) * 2;
        bbx[g] = make_float2(gb[0], gb[1]);
    }
    const int n = num_person[b];
    __syncwarp();

    // ---- per-proposal setup: 4 proposals per lane ----
    ull cxx[4], cyy[4], czz[4];
    int bk[4][4];
    #pragma unroll
    for (int k = 0; k < 4; ++k) {
        const int p = lane + (k << 5);
        const int* ti = topk_index + ((size_t)b * PP + p) * 3;
        float cx = (float)ti[0] * SCX + BX;
        float cy = (float)ti[1] * SCY + BY;
        float cz = (float)ti[2] * SCZ + BZ;
        cxx[k] = pack2(cx, cx);
        cyy[k] = pack2(cy, cy);
        czz[k] = pack2(cz, cz);
        bk[k][0] = bk[k][1] = bk[k][2] = bk[k][3] = 0x7FFFFFFF;
    }

    const ulonglong2* px = (const ulonglong2*)nx;
    const ulonglong2* py = (const ulonglong2*)ny;
    const ulonglong2* pz = (const ulonglong2*)nz;
    const ulonglong2* ph = (const ulonglong2*)hh;

    // ---- main scan: 4 LDS.128 feed 16 (p,g) pairs per lane ----
    const int nb = n >> 2;
    #pragma unroll 2
    for (int q = 0; q < nb; ++q) {
        ulonglong2 X = px[q];
        ulonglong2 Y = py[q];
        ulonglong2 Z = pz[q];
        ulonglong2 H = ph[q];

        #pragma unroll
        for (int k = 0; k < 4; ++k) {
            ull eA = fma2(cxx[k], X.x, fma2(cyy[k], Y.x, fma2(czz[k], Z.x, H.x)));
            ull eB = fma2(cxx[k], X.y, fma2(cyy[k], Y.y, fma2(czz[k], Z.y, H.y)));
            float s0, s1, s2, s3;
            unpack2(eA, s0, s1);
            unpack2(eB, s2, s3);
            bk[k][0] = min(bk[k][0], (__float_as_int(s0) & KEYMASK) | q);
            bk[k][1] = min(bk[k][1], (__float_as_int(s1) & KEYMASK) | q);
            bk[k][2] = min(bk[k][2], (__float_as_int(s2) & KEYMASK) | q);
            bk[k][3] = min(bk[k][3], (__float_as_int(s3) & KEYMASK) | q);
        }
    }

    // ---- finalize each of this lane's 4 proposals ----
    #pragma unroll
    for (int k = 0; k < 4; ++k) {
        float cx, cxd, cy, cyd, cz, czd;
        unpack2(cxx[k], cx, cxd);
        unpack2(cyy[k], cy, cyd);
        unpack2(czz[k], cz, czd);

        // merge 4 residue chains (masked value, strict <; residue order = g order)
        int best_mv = bk[k][0] & KEYMASK;
        int bi = ((bk[k][0] & 31) << 2);
        { int mv = bk[k][1] & KEYMASK; if (mv < best_mv) { best_mv = mv; bi = ((bk[k][1] & 31) << 2) + 1; } }
        { int mv = bk[k][2] & KEYMASK; if (mv < best_mv) { best_mv = mv; bi = ((bk[k][2] & 31) << 2) + 2; } }
        { int mv = bk[k][3] & KEYMASK; if (mv < best_mv) { best_mv = mv; bi = ((bk[k][3] & 31) << 2) + 3; } }

        // scalar tail (g >= nb*4): same masked ordering, strict < keeps earlier g
        for (int g = (nb << 2); g < n; ++g) {
            float e = __fmaf_rn(cx, nx[g], __fmaf_rn(cy, ny[g], __fmaf_rn(cz, nz[g], hh[g])));
            int mv = __float_as_int(e) & KEYMASK;
            if (mv < best_mv) { best_mv = mv; bi = g; }
        }

        // exact threshold recheck: d2 <= 500^2  <=>  e+EOFF <= 0.5*(500^2-cc)+EOFF
        const float cc = __fmaf_rn(cz, cz, __fmaf_rn(cy, cy, cx * cx));
        const float e_best = __fmaf_rn(cx, nx[bi],
                            __fmaf_rn(cy, ny[bi],
                            __fmaf_rn(cz, nz[bi], hh[bi])));
        const float thresh_e = __fmaf_rn(-0.5f, cc, 0.5f * DIST_THRESH_SQ + EOFF);
        const bool matched = !(e_best > thresh_e);
        const float p2g = matched ? (float)bi : -1.0f;

        // per-proposal loads deferred to epilogue (shorter live ranges)
        const int p = lane + (k << 5);
        const float conf = topk_confs[(size_t)b * PP + p];
        const float* mp = match_bbox_preds + ((size_t)b * PP + p) * 2;
        const float pb0 = mp[0];
        const float pb1 = mp[1];

        float2 mb = bbx[bi];
        bool ow = matched && ((pb0 < mb.x - BBOX_THRESH) || (pb1 < mb.y - BBOX_THRESH));
        const float o5 = ow ? mb.x : pb0;
        const float o6 = ow ? mb.y : pb1;

        float* so = s_out[w] + p * 7;   // stride 7 -> conflict-free
        so[0] = cx; so[1] = cy; so[2] = cz;
        so[3] = p2g; so[4] = conf;
        so[5] = o5;  so[6] = o6;
    }
    __syncwarp();

    // ---- coalesced output: 896 floats = 224 float4, 7 per lane ----
    const float4* src = (const float4*)s_out[w];
    float4* dst = (float4*)(out + (size_t)b * (PP * 7));
    #pragma unroll
    for (int i = lane; i < 224; i += 32)
        dst[i] = src[i];
}

extern "C" void kernel_launch(void* const* d_in, const int* in_sizes, int n_in,
                              void* d_out, int out_size)
{
    const int*   topk_index       = (const int*)  d_in[0];
    const float* topk_confs       = (const float*)d_in[1];
    const float* match_bbox_preds = (const float*)d_in[2];
    const float* roots_3d         = (const float*)d_in[3];
    const float* gt_bbox          = (const float*)d_in[4];
    const int*   num_person       = (const int*)  d_in[5];
    float* out = (float*)d_out;

    proposal_layer_kernel<<<BB / 4, 128>>>(topk_index, topk_confs, match_bbox_preds,
                                           roots_3d, gt_bbox, num_person, out);
}

// round 8
// speedup vs baseline: 1.1233x; 1.1233x over previous
#include <cuda_runtime.h>

#define BB 4096
#define PP 128
#define GG 128

#define SCX (8000.0f / 79.0f)
#define SCY (8000.0f / 79.0f)
#define SCZ (2000.0f / 19.0f)
#define BX (-4000.0f)
#define BY (-4000.0f)
#define BZ (0.0f)

#define DIST_THRESH_SQ (500.0f * 500.0f)
#define BBOX_THRESH 0.1f
#define EOFF 2.0e8f              // offset keeping e positive for finite inputs

typedef unsigned long long ull;

// ---- packed f32x2 helpers (sm_103a) ----
__device__ __forceinline__ ull pack2(float lo, float hi) {
    ull r;
    asm("mov.b64 %0, {%1, %2};" : "=l"(r) : "f"(lo), "f"(hi));
    return r;
}
__device__ __forceinline__ void unpack2(ull v, float& lo, float& hi) {
    asm("mov.b64 {%0, %1}, %2;" : "=f"(lo), "=f"(hi) : "l"(v));
}
__device__ __forceinline__ ull fma2(ull a, ull b, ull c) {
    ull r;
    asm("fma.rn.f32x2 %0, %1, %2, %3;" : "=l"(r) : "l"(a), "l"(b), "l"(c));
    return r;
}

__global__ __launch_bounds__(PP, 8)
void proposal_layer_kernel(const int*   __restrict__ topk_index,      // [B,P,3]
                           const float* __restrict__ topk_confs,      // [B,P]
                           const float* __restrict__ match_bbox_preds,// [B,P,2]
                           const float* __restrict__ roots_3d,        // [B,G,3]
                           const float* __restrict__ gt_bbox,         // [B,G,2]
                           const int*   __restrict__ num_person,      // [B]
                           float*       __restrict__ out)             // [B,P,7]
{
    const int b = blockIdx.x;
    const int p = threadIdx.x;  // 0..127, one proposal per thread

    __shared__ __align__(16) float s_nx[GG];   // -rx
    __shared__ __align__(16) float s_ny[GG];   // -ry
    __shared__ __align__(16) float s_nz[GG];   // -rz
    __shared__ __align__(16) float s_h [GG];   // |r|^2/2 + EOFF, or +INF if g >= n
    __shared__ float2 s_bbox[GG];
    __shared__ float  s_out[PP * 7];

    const int n = num_person[b];  // uniform load, broadcast

    // ---- stage gt data; pad h with +INF past n (kills the tail loop) ----
    {
        const float* r = roots_3d + ((size_t)b * GG + p) * 3;
        float rx = r[0], ry = r[1], rz = r[2];
        s_nx[p] = -rx;
        s_ny[p] = -ry;
        s_nz[p] = -rz;
        float hv = __fmaf_rn(0.5f, __fmaf_rn(rz, rz, __fmaf_rn(ry, ry, rx * rx)), EOFF);
        s_h[p]  = (p < n) ? hv : __int_as_float(0x7F800000);
        const float* gb = gt_bbox + ((size_t)b * GG + p) * 2;
        s_bbox[p] = make_float2(gb[0], gb[1]);
    }
    __syncthreads();

    // ---- per-proposal inputs, ALL loaded before the scan (overlap L2 latency) ----
    const int* ti = topk_index + ((size_t)b * PP + p) * 3;
    const float cx = (float)ti[0] * SCX + BX;
    const float cy = (float)ti[1] * SCY + BY;
    const float cz = (float)ti[2] * SCZ + BZ;

    const float conf = topk_confs[(size_t)b * PP + p];
    const float* mp = match_bbox_preds + ((size_t)b * PP + p) * 2;
    const float pb0 = mp[0];
    const float pb1 = mp[1];

    const ull cxx = pack2(cx, cx);
    const ull cyy = pack2(cy, cy);
    const ull czz = pack2(cz, cz);

    const ulonglong2* px = (const ulonglong2*)s_nx;
    const ulonglong2* py = (const ulonglong2*)s_ny;
    const ulonglong2* pz = (const ulonglong2*)s_nz;
    const ulonglong2* ph = (const ulonglong2*)s_h;

    // ---- scan: 4 residue chains, e(g) = h_g - c.r_g + EOFF; INF pads never win ----
    float b0 = __int_as_float(0x7F800000), b1 = b0, b2 = b0, b3 = b0;
    int q0 = 0, q1 = 0, q2 = 0, q3 = 0;

    const int nbc = (n + 3) >> 2;   // ceil(n/4); padded region is +INF
    #pragma unroll 4
    for (int q = 0; q < nbc; ++q) {
        ulonglong2 X = px[q];   // LDS.128 broadcast
        ulonglong2 Y = py[q];
        ulonglong2 Z = pz[q];
        ulonglong2 H = ph[q];

        ull eA = fma2(cxx, X.x, fma2(cyy, Y.x, fma2(czz, Z.x, H.x)));
        ull eB = fma2(cxx, X.y, fma2(cyy, Y.y, fma2(czz, Z.y, H.y)));
        float s0, s1, s2, s3;
        unpack2(eA, s0, s1);
        unpack2(eB, s2, s3);

        if (s0 < b0) { b0 = s0; q0 = q; }   // strict <: first min wins
        if (s1 < b1) { b1 = s1; q1 = q; }
        if (s2 < b2) { b2 = s2; q2 = q; }
        if (s3 < b3) { b3 = s3; q3 = q; }
    }

    // merge chains (residue order = g order within a block; strict <)
    float bd = b0; int bi = (q0 << 2);
    if (b1 < bd) { bd = b1; bi = (q1 << 2) + 1; }
    if (b2 < bd) { bd = b2; bi = (q2 << 2) + 2; }
    if (b3 < bd) { bd = b3; bi = (q3 << 2) + 3; }

    // threshold: d2 <= 500^2  <=>  e+EOFF <= 0.5*(500^2 - cc) + EOFF  (exact fp32)
    const float cc = __fmaf_rn(cz, cz, __fmaf_rn(cy, cy, cx * cx));
    const float thresh_e = __fmaf_rn(-0.5f, cc, 0.5f * DIST_THRESH_SQ + EOFF);
    const bool matched = !(bd > thresh_e);
    const float p2g = matched ? (float)bi : -1.0f;

    float2 mb = s_bbox[bi];
    bool ow = matched && ((pb0 < mb.x - BBOX_THRESH) || (pb1 < mb.y - BBOX_THRESH));
    const float o5 = ow ? mb.x : pb0;
    const float o6 = ow ? mb.y : pb1;

    // ---- stage [P,7] tile (stride 7 -> conflict-free), coalesced float4 store ----
    float* so = s_out + p * 7;
    so[0] = cx; so[1] = cy; so[2] = cz;
    so[3] = p2g; so[4] = conf;
    so[5] = o5;  so[6] = o6;
    __syncthreads();

    const float4* src = (const float4*)s_out;
    float4* dst = (float4*)(out + (size_t)b * (PP * 7));
    #pragma unroll
    for (int i = p; i < 224; i += PP)   // 896 floats = 224 float4
        dst[i] = src[i];
}

extern "C" void kernel_launch(void* const* d_in, const int* in_sizes, int n_in,
                              void* d_out, int out_size)
{
    const int*   topk_index       = (const int*)  d_in[0];
    const float* topk_confs       = (const float*)d_in[1];
    const float* match_bbox_preds = (const float*)d_in[2];
    const float* roots_3d         = (const float*)d_in[3];
    const float* gt_bbox          = (const float*)d_in[4];
    const int*   num_person       = (const int*)  d_in[5];
    float* out = (float*)d_out;

    proposal_layer_kernel<<<BB, PP>>>(topk_index, topk_confs, match_bbox_preds,
                                      roots_3d, gt_bbox, num_person, out);
}